// round 1
// baseline (speedup 1.0000x reference)
#include <cuda_runtime.h>

// SKA: out[b, g*32+c, h, w] = sum_{di,dj} x[b, g*32+c, h+di-2, w+dj-2] * w[b, g, di*5+dj, h, w]
// Shapes: x [8,256,64,64] f32, w [8,8,25,64,64] f32, out [8,256,64,64] f32.

#define B_  8
#define C_  256
#define H_  64
#define W_  64
#define G_  8
#define CG_ 32
#define NC_ 4   // channels per thread

__global__ __launch_bounds__(256, 2)
void SKA_60387240182286_kernel(const float* __restrict__ x,
                               const float* __restrict__ wgt,
                               float* __restrict__ out)
{
    const int tid  = threadIdx.x;
    const int wq   = tid & 15;          // 0..15: which 4-wide pixel group along W
    const int hsub = (tid >> 4) & 1;    // 0..1: row within the block's 2-row strip
    const int cblk = tid >> 5;          // 0..7: channel block within group (warp-granular)

    const int bg    = blockIdx.x;       // 0..63 = b*8 + g
    const int hpair = blockIdx.y;       // 0..31
    const int b = bg >> 3;
    const int g = bg & 7;
    const int h = hpair * 2 + hsub;
    const int w0 = wq * 4;
    const int c0 = g * CG_ + cblk * NC_;

    // base pointers
    const float* xbase = x + ((size_t)(b * C_ + c0)) * (H_ * W_);
    const float* wbase = wgt + (((size_t)bg * 25) * H_ + h) * W_ + w0;

    float acc[NC_][4];
#pragma unroll
    for (int c = 0; c < NC_; ++c) {
        acc[c][0] = 0.f; acc[c][1] = 0.f; acc[c][2] = 0.f; acc[c][3] = 0.f;
    }

    const float4 z4 = make_float4(0.f, 0.f, 0.f, 0.f);
    const bool left_edge  = (wq == 0);
    const bool right_edge = (wq == 15);

#pragma unroll
    for (int di = 0; di < 5; ++di) {
        const int hy = h + di - 2;
        const bool rv = (hy >= 0) && (hy < H_);

        // x window per channel: 12 floats covering columns [w0-4, w0+7]
        float xv[NC_][12];
#pragma unroll
        for (int c = 0; c < NC_; ++c) {
            const float* row = xbase + ((size_t)c * H_ + hy) * W_;
            const float4* xp = (const float4*)(row + w0 - 4);
            float4 a = (rv && !left_edge)  ? xp[0] : z4;
            float4 m = rv                  ? xp[1] : z4;
            float4 r = (rv && !right_edge) ? xp[2] : z4;
            xv[c][0] = a.x; xv[c][1] = a.y; xv[c][2]  = a.z; xv[c][3]  = a.w;
            xv[c][4] = m.x; xv[c][5] = m.y; xv[c][6]  = m.z; xv[c][7]  = m.w;
            xv[c][8] = r.x; xv[c][9] = r.y; xv[c][10] = r.z; xv[c][11] = r.w;
        }

#pragma unroll
        for (int dj = 0; dj < 5; ++dj) {
            const int k = di * 5 + dj;
            const float4 wv = *(const float4*)(wbase + (size_t)k * (H_ * W_));
#pragma unroll
            for (int c = 0; c < NC_; ++c) {
                // output pixel p at column w0+p uses x column (w0+p) + dj - 2
                // -> window index p + dj + 2
                acc[c][0] = fmaf(xv[c][dj + 2], wv.x, acc[c][0]);
                acc[c][1] = fmaf(xv[c][dj + 3], wv.y, acc[c][1]);
                acc[c][2] = fmaf(xv[c][dj + 4], wv.z, acc[c][2]);
                acc[c][3] = fmaf(xv[c][dj + 5], wv.w, acc[c][3]);
            }
        }
    }

    float* obase = out + (((size_t)(b * C_ + c0)) * H_ + h) * W_ + w0;
#pragma unroll
    for (int c = 0; c < NC_; ++c) {
        *(float4*)(obase + (size_t)c * (H_ * W_)) =
            make_float4(acc[c][0], acc[c][1], acc[c][2], acc[c][3]);
    }
}

extern "C" void kernel_launch(void* const* d_in, const int* in_sizes, int n_in,
                              void* d_out, int out_size)
{
    const float* x   = (const float*)d_in[0];
    const float* wgt = (const float*)d_in[1];
    float* out = (float*)d_out;

    dim3 grid(B_ * G_, H_ / 2);   // (64, 32) blocks
    SKA_60387240182286_kernel<<<grid, 256>>>(x, wgt, out);
}

// round 2
// speedup vs baseline: 1.2055x; 1.2055x over previous
#include <cuda_runtime.h>

// SKA: out[b, g*32+c, h, w] = sum_{di,dj} x[b, g*32+c, h+di-2, w+dj-2] * w[b, g, di*5+dj, h, w]
// x [8,256,64,64] f32, w [8,8,25,64,64] f32, out [8,256,64,64] f32.

#define B_  8
#define C_  256
#define H_  64
#define W_  64
#define G_  8
#define CG_ 32
#define NC_ 2   // channels per thread

__global__ __launch_bounds__(256, 4)
void SKA_60387240182286_kernel(const float* __restrict__ x,
                               const float* __restrict__ wgt,
                               float* __restrict__ out)
{
    const int tid  = threadIdx.x;
    const int wq   = tid & 15;          // 0..15: 4-wide pixel group along W
    const int hsub = (tid >> 4) & 1;    // 0..1: row within 2-row strip
    const int cblk = tid >> 5;          // 0..7: channel pair within the 16-ch half

    const int bg    = blockIdx.x;       // 0..63 = b*8 + g
    const int hpair = blockIdx.y;       // 0..31
    const int chalf = blockIdx.z;       // 0..1: which 16 channels of the group
    const int b = bg >> 3;
    const int g = bg & 7;
    const int h = hpair * 2 + hsub;
    const int w0 = wq * 4;
    const int c0 = g * CG_ + chalf * 16 + cblk * NC_;

    const float* xbase = x + ((size_t)(b * C_ + c0)) * (H_ * W_);
    const float* wbase = wgt + (((size_t)bg * 25) * H_ + h) * W_ + w0;

    float acc[NC_][4];
#pragma unroll
    for (int c = 0; c < NC_; ++c) {
        acc[c][0] = 0.f; acc[c][1] = 0.f; acc[c][2] = 0.f; acc[c][3] = 0.f;
    }

    const float2 z2 = make_float2(0.f, 0.f);
    const float4 z4 = make_float4(0.f, 0.f, 0.f, 0.f);
    const bool left_edge  = (wq == 0);
    const bool right_edge = (wq == 15);

#pragma unroll
    for (int di = 0; di < 5; ++di) {
        const int hy = h + di - 2;
        const bool rv = (hy >= 0) && (hy < H_);

        // exact x window per channel: 8 floats covering columns [w0-2, w0+5]
        float xv[NC_][8];
#pragma unroll
        for (int c = 0; c < NC_; ++c) {
            const float* row = xbase + ((size_t)c * H_ + hy) * W_;
            float2 a = (rv && !left_edge)  ? *(const float2*)(row + w0 - 2) : z2;
            float4 m = rv                  ? *(const float4*)(row + w0)     : z4;
            float2 r = (rv && !right_edge) ? *(const float2*)(row + w0 + 4) : z2;
            xv[c][0] = a.x; xv[c][1] = a.y;
            xv[c][2] = m.x; xv[c][3] = m.y; xv[c][4] = m.z; xv[c][5] = m.w;
            xv[c][6] = r.x; xv[c][7] = r.y;
        }

#pragma unroll
        for (int dj = 0; dj < 5; ++dj) {
            const int k = di * 5 + dj;
            const float4 wv = *(const float4*)(wbase + (size_t)k * (H_ * W_));
#pragma unroll
            for (int c = 0; c < NC_; ++c) {
                // output pixel p (col w0+p), tap dj -> x col w0+p+dj-2 -> window idx p+dj
                acc[c][0] = fmaf(xv[c][dj + 0], wv.x, acc[c][0]);
                acc[c][1] = fmaf(xv[c][dj + 1], wv.y, acc[c][1]);
                acc[c][2] = fmaf(xv[c][dj + 2], wv.z, acc[c][2]);
                acc[c][3] = fmaf(xv[c][dj + 3], wv.w, acc[c][3]);
            }
        }
    }

    float* obase = out + (((size_t)(b * C_ + c0)) * H_ + h) * W_ + w0;
#pragma unroll
    for (int c = 0; c < NC_; ++c) {
        *(float4*)(obase + (size_t)c * (H_ * W_)) =
            make_float4(acc[c][0], acc[c][1], acc[c][2], acc[c][3]);
    }
}

extern "C" void kernel_launch(void* const* d_in, const int* in_sizes, int n_in,
                              void* d_out, int out_size)
{
    const float* x   = (const float*)d_in[0];
    const float* wgt = (const float*)d_in[1];
    float* out = (float*)d_out;

    dim3 grid(B_ * G_, H_ / 2, 2);   // (64, 32, 2) = 4096 blocks
    SKA_60387240182286_kernel<<<grid, 256>>>(x, wgt, out);
}